// round 2
// baseline (speedup 1.0000x reference)
#include <cuda_runtime.h>

#define M_TOT 8192
#define EMBD  1024
#define TSEQ  2048
#define NB    4
#define NH    16
#define HDI   64

// Scratch (static device allocations are allowed)
__device__ float g_q[M_TOT * EMBD];
__device__ float g_k[M_TOT * EMBD];
__device__ float g_v[M_TOT * EMBD];
__device__ float g_attn[M_TOT * EMBD];

// ---------------------------------------------------------------------------
// QKV projection: Y = X @ W^T + b, written into [B,H,T,hd] scratch.
// 128x128x16 tile, 256 threads, 8x8 microtile (split 4+4 rows/cols).
// ---------------------------------------------------------------------------
__global__ __launch_bounds__(256) void qkv_kernel(
    const float* __restrict__ X,
    const float* __restrict__ Wq, const float* __restrict__ bq,
    const float* __restrict__ Wk, const float* __restrict__ bk,
    const float* __restrict__ Wv, const float* __restrict__ bv)
{
    const float* W; const float* bias; float* out;
    if (blockIdx.z == 0)      { W = Wq; bias = bq; out = g_q; }
    else if (blockIdx.z == 1) { W = Wk; bias = bk; out = g_k; }
    else                      { W = Wv; bias = bv; out = g_v; }

    __shared__ float As[16][132];
    __shared__ float Bs[16][132];

    const int tid = threadIdx.x;
    const int tx = tid & 15, ty = tid >> 4;
    const int m0 = blockIdx.x * 128, n0 = blockIdx.y * 128;
    const int lrow = tid >> 2, lk = (tid & 3) * 4;

    float acc[8][8];
#pragma unroll
    for (int i = 0; i < 8; i++)
#pragma unroll
        for (int j = 0; j < 8; j++) acc[i][j] = 0.f;

    for (int k0 = 0; k0 < EMBD; k0 += 16) {
#pragma unroll
        for (int r = 0; r < 2; r++) {
            int row = lrow + 64 * r;
            float4 va = *(const float4*)(X + (size_t)(m0 + row) * EMBD + k0 + lk);
            As[lk + 0][row] = va.x; As[lk + 1][row] = va.y;
            As[lk + 2][row] = va.z; As[lk + 3][row] = va.w;
            float4 vb = *(const float4*)(W + (size_t)(n0 + row) * EMBD + k0 + lk);
            Bs[lk + 0][row] = vb.x; Bs[lk + 1][row] = vb.y;
            Bs[lk + 2][row] = vb.z; Bs[lk + 3][row] = vb.w;
        }
        __syncthreads();
#pragma unroll
        for (int kk = 0; kk < 16; kk++) {
            float4 a0 = *(float4*)&As[kk][4 * ty];
            float4 a1 = *(float4*)&As[kk][64 + 4 * ty];
            float4 b0 = *(float4*)&Bs[kk][4 * tx];
            float4 b1 = *(float4*)&Bs[kk][64 + 4 * tx];
            float a[8] = {a0.x, a0.y, a0.z, a0.w, a1.x, a1.y, a1.z, a1.w};
            float b[8] = {b0.x, b0.y, b0.z, b0.w, b1.x, b1.y, b1.z, b1.w};
#pragma unroll
            for (int i = 0; i < 8; i++)
#pragma unroll
                for (int j = 0; j < 8; j++) acc[i][j] = fmaf(a[i], b[j], acc[i][j]);
        }
        __syncthreads();
    }

    // Epilogue: bias + scatter into [B,H,T,hd]
#pragma unroll
    for (int i = 0; i < 8; i++) {
        int row = m0 + ((i < 4) ? (4 * ty + i) : (64 + 4 * ty + i - 4));
        int bb = row >> 11, tt = row & 2047;
#pragma unroll
        for (int jh = 0; jh < 2; jh++) {
            int col = n0 + jh * 64 + 4 * tx;
            int h = col >> 6, d = col & 63;
            float4 v;
            v.x = acc[i][jh * 4 + 0] + bias[col + 0];
            v.y = acc[i][jh * 4 + 1] + bias[col + 1];
            v.z = acc[i][jh * 4 + 2] + bias[col + 2];
            v.w = acc[i][jh * 4 + 3] + bias[col + 3];
            *(float4*)(out + ((size_t)((bb * NH + h) * TSEQ + tt)) * HDI + d) = v;
        }
    }
}

// ---------------------------------------------------------------------------
// Flash attention, fp32 online softmax. 64 queries x 64 keys per tile.
// grid: (T/64, B*H), 256 threads, 4x4 microtiles.
// smem: Qs[64][68] (Q^T), KP[64][68] (K^T then P^T), Vs[64][64]
// ---------------------------------------------------------------------------
#define ATTN_SMEM ((2 * 64 * 68 + 64 * 64) * 4)

__global__ __launch_bounds__(256) void attn_kernel()
{
    extern __shared__ float sm[];
    float* Qs = sm;              // [64][68], transposed: Qs[d][q]
    float* KP = sm + 64 * 68;    // [64][68], K^T then P^T
    float* Vs = sm + 2 * 64 * 68;// [64][64], natural: Vs[j][d]

    const int tid = threadIdx.x;
    const int tx = tid & 15, ty = tid >> 4;
    const int bh = blockIdx.y, q0 = blockIdx.x * 64;
    const float* Qg = g_q + (size_t)bh * TSEQ * HDI;
    const float* Kg = g_k + (size_t)bh * TSEQ * HDI;
    const float* Vg = g_v + (size_t)bh * TSEQ * HDI;
    const int ld0 = (tid & 15) * 4, lrow = tid >> 4;

    // Load Q tile transposed (once per CTA)
#pragma unroll
    for (int rep = 0; rep < 4; rep++) {
        int q = lrow + 16 * rep;
        float4 v = *(const float4*)(Qg + (size_t)(q0 + q) * HDI + ld0);
        Qs[(ld0 + 0) * 68 + q] = v.x; Qs[(ld0 + 1) * 68 + q] = v.y;
        Qs[(ld0 + 2) * 68 + q] = v.z; Qs[(ld0 + 3) * 68 + q] = v.w;
    }

    float m_run[4], l_run[4], o[4][4];
#pragma unroll
    for (int i = 0; i < 4; i++) {
        m_run[i] = -1e30f; l_run[i] = 0.f;
#pragma unroll
        for (int x = 0; x < 4; x++) o[i][x] = 0.f;
    }

    for (int j0 = 0; j0 < TSEQ; j0 += 64) {
        __syncthreads();  // previous tile's KP/Vs consumers done (also orders Q store)
#pragma unroll
        for (int rep = 0; rep < 4; rep++) {
            int j = lrow + 16 * rep;
            float4 v = *(const float4*)(Kg + (size_t)(j0 + j) * HDI + ld0);
            KP[(ld0 + 0) * 68 + j] = v.x; KP[(ld0 + 1) * 68 + j] = v.y;
            KP[(ld0 + 2) * 68 + j] = v.z; KP[(ld0 + 3) * 68 + j] = v.w;
            float4 w = *(const float4*)(Vg + (size_t)(j0 + j) * HDI + ld0);
            *(float4*)(Vs + j * 64 + ld0) = w;
        }
        __syncthreads();

        // S = Q K^T (4x4 per thread)
        float s[4][4];
#pragma unroll
        for (int i = 0; i < 4; i++)
#pragma unroll
            for (int j = 0; j < 4; j++) s[i][j] = 0.f;
#pragma unroll
        for (int d = 0; d < 64; d++) {
            float4 a4 = *(float4*)(Qs + d * 68 + 4 * ty);
            float4 b4 = *(float4*)(KP + d * 68 + 4 * tx);
            float a[4] = {a4.x, a4.y, a4.z, a4.w};
            float b[4] = {b4.x, b4.y, b4.z, b4.w};
#pragma unroll
            for (int i = 0; i < 4; i++)
#pragma unroll
                for (int j = 0; j < 4; j++) s[i][j] = fmaf(a[i], b[j], s[i][j]);
        }

        // Online softmax: rows 4*ty+i reduce across the 16 tx lanes (same half-warp)
#pragma unroll
        for (int i = 0; i < 4; i++) {
            float mx = -1e30f;
#pragma unroll
            for (int j = 0; j < 4; j++) mx = fmaxf(mx, s[i][j] * 0.125f);
#pragma unroll
            for (int off = 8; off; off >>= 1)
                mx = fmaxf(mx, __shfl_xor_sync(0xffffffffu, mx, off));
            float mnew = fmaxf(m_run[i], mx);
            float alpha = __expf(m_run[i] - mnew);
            float rs = 0.f;
#pragma unroll
            for (int j = 0; j < 4; j++) {
                s[i][j] = __expf(s[i][j] * 0.125f - mnew);
                rs += s[i][j];
            }
#pragma unroll
            for (int off = 8; off; off >>= 1)
                rs += __shfl_xor_sync(0xffffffffu, rs, off);
            l_run[i] = l_run[i] * alpha + rs;
            m_run[i] = mnew;
#pragma unroll
            for (int x = 0; x < 4; x++) o[i][x] *= alpha;
        }

        __syncthreads();  // all S-gemm reads of KP done before overwrite
        // Write P^T into KP
#pragma unroll
        for (int i = 0; i < 4; i++)
#pragma unroll
            for (int j = 0; j < 4; j++)
                KP[(4 * tx + j) * 68 + 4 * ty + i] = s[i][j];
        __syncthreads();

        // O += P V
#pragma unroll
        for (int j = 0; j < 64; j++) {
            float4 a4 = *(float4*)(KP + j * 68 + 4 * ty);
            float4 b4 = *(float4*)(Vs + j * 64 + 4 * tx);
            float a[4] = {a4.x, a4.y, a4.z, a4.w};
            float b[4] = {b4.x, b4.y, b4.z, b4.w};
#pragma unroll
            for (int i = 0; i < 4; i++)
#pragma unroll
                for (int x = 0; x < 4; x++) o[i][x] = fmaf(a[i], b[x], o[i][x]);
        }
    }

    // Write back: [B,T,EMB] row-major so out-proj is a plain GEMM
    const int b = bh >> 4, h = bh & 15;
#pragma unroll
    for (int i = 0; i < 4; i++) {
        float inv = 1.f / l_run[i];
        int q = q0 + 4 * ty + i;
        float4 v;
        v.x = o[i][0] * inv; v.y = o[i][1] * inv;
        v.z = o[i][2] * inv; v.w = o[i][3] * inv;
        *(float4*)(g_attn + ((size_t)(b * TSEQ + q)) * EMBD + h * HDI + 4 * tx) = v;
    }
}

// ---------------------------------------------------------------------------
// Output projection: out = attn @ Wo^T + bo
// ---------------------------------------------------------------------------
__global__ __launch_bounds__(256) void proj_kernel(
    const float* __restrict__ Wo, const float* __restrict__ bo,
    float* __restrict__ out)
{
    __shared__ float As[16][132];
    __shared__ float Bs[16][132];

    const int tid = threadIdx.x;
    const int tx = tid & 15, ty = tid >> 4;
    const int m0 = blockIdx.x * 128, n0 = blockIdx.y * 128;
    const int lrow = tid >> 2, lk = (tid & 3) * 4;

    float acc[8][8];
#pragma unroll
    for (int i = 0; i < 8; i++)
#pragma unroll
        for (int j = 0; j < 8; j++) acc[i][j] = 0.f;

    for (int k0 = 0; k0 < EMBD; k0 += 16) {
#pragma unroll
        for (int r = 0; r < 2; r++) {
            int row = lrow + 64 * r;
            float4 va = *(const float4*)(g_attn + (size_t)(m0 + row) * EMBD + k0 + lk);
            As[lk + 0][row] = va.x; As[lk + 1][row] = va.y;
            As[lk + 2][row] = va.z; As[lk + 3][row] = va.w;
            float4 vb = *(const float4*)(Wo + (size_t)(n0 + row) * EMBD + k0 + lk);
            Bs[lk + 0][row] = vb.x; Bs[lk + 1][row] = vb.y;
            Bs[lk + 2][row] = vb.z; Bs[lk + 3][row] = vb.w;
        }
        __syncthreads();
#pragma unroll
        for (int kk = 0; kk < 16; kk++) {
            float4 a0 = *(float4*)&As[kk][4 * ty];
            float4 a1 = *(float4*)&As[kk][64 + 4 * ty];
            float4 b0 = *(float4*)&Bs[kk][4 * tx];
            float4 b1 = *(float4*)&Bs[kk][64 + 4 * tx];
            float a[8] = {a0.x, a0.y, a0.z, a0.w, a1.x, a1.y, a1.z, a1.w};
            float b[8] = {b0.x, b0.y, b0.z, b0.w, b1.x, b1.y, b1.z, b1.w};
#pragma unroll
            for (int i = 0; i < 8; i++)
#pragma unroll
                for (int j = 0; j < 8; j++) acc[i][j] = fmaf(a[i], b[j], acc[i][j]);
        }
        __syncthreads();
    }

#pragma unroll
    for (int i = 0; i < 8; i++) {
        int row = m0 + ((i < 4) ? (4 * ty + i) : (64 + 4 * ty + i - 4));
#pragma unroll
        for (int jh = 0; jh < 2; jh++) {
            int col = n0 + jh * 64 + 4 * tx;
            float4 v;
            v.x = acc[i][jh * 4 + 0] + bo[col + 0];
            v.y = acc[i][jh * 4 + 1] + bo[col + 1];
            v.z = acc[i][jh * 4 + 2] + bo[col + 2];
            v.w = acc[i][jh * 4 + 3] + bo[col + 3];
            *(float4*)(out + (size_t)row * EMBD + col) = v;
        }
    }
}

// ---------------------------------------------------------------------------
extern "C" void kernel_launch(void* const* d_in, const int* in_sizes, int n_in,
                              void* d_out, int out_size)
{
    const float* x  = (const float*)d_in[0];
    const float* Wq = (const float*)d_in[1];
    const float* bq = (const float*)d_in[2];
    const float* Wk = (const float*)d_in[3];
    const float* bk = (const float*)d_in[4];
    const float* Wv = (const float*)d_in[5];
    const float* bv = (const float*)d_in[6];
    const float* Wo = (const float*)d_in[7];
    const float* bo = (const float*)d_in[8];
    float* out = (float*)d_out;

    cudaFuncSetAttribute(attn_kernel, cudaFuncAttributeMaxDynamicSharedMemorySize,
                         ATTN_SMEM);

    dim3 gq(M_TOT / 128, EMBD / 128, 3);
    qkv_kernel<<<gq, 256>>>(x, Wq, bq, Wk, bk, Wv, bv);

    dim3 ga(TSEQ / 64, NB * NH);
    attn_kernel<<<ga, 256, ATTN_SMEM>>>();

    dim3 go(M_TOT / 128, EMBD / 128);
    proj_kernel<<<go, 256>>>(Wo, bo, out);
}

// round 3
// speedup vs baseline: 2.4969x; 2.4969x over previous
#include <cuda_runtime.h>

#define M_TOT 8192
#define EMBD  1024
#define TSEQ  2048
#define NB    4
#define NH    16
#define HDI   64

// Scratch
__device__ float g_q[M_TOT * EMBD];
__device__ float g_k[M_TOT * EMBD];
__device__ float g_v[M_TOT * EMBD];
__device__ float g_attn[M_TOT * EMBD];

__device__ __forceinline__ unsigned f2tf(float f) {
    unsigned r; asm("cvt.rna.tf32.f32 %0, %1;" : "=r"(r) : "f"(f)); return r;
}

// D += A*B, m16n8k8 tf32, D==C in place
__device__ __forceinline__ void mma8(float* d, const unsigned* a, const unsigned* b) {
    asm volatile("mma.sync.aligned.m16n8k8.row.col.f32.tf32.tf32.f32 "
        "{%0,%1,%2,%3}, {%4,%5,%6,%7}, {%8,%9}, {%0,%1,%2,%3};"
        : "+f"(d[0]), "+f"(d[1]), "+f"(d[2]), "+f"(d[3])
        : "r"(a[0]), "r"(a[1]), "r"(a[2]), "r"(a[3]), "r"(b[0]), "r"(b[1]));
}

// ---------------------------------------------------------------------------
// tf32 GEMM: Y = X @ W^T + bias.  128x128x32 tiles, 256 thr, 8 warps (4m x 2n),
// warp tile 32x64 (2 m16-tiles x 8 n8-tiles). smem stride 36 (conflict-free).
// ---------------------------------------------------------------------------
#define GEMM_SMEM (2 * 2 * 128 * 36 * 4)

template<int SCATTER>
__device__ __forceinline__ void gemm_body(
    const float* __restrict__ A, const float* __restrict__ Bw,
    const float* __restrict__ bias, float* __restrict__ out,
    int bx, int by)
{
    extern __shared__ unsigned smu[];
    unsigned* As = smu;                  // [2][128*36]
    unsigned* Bs = smu + 2 * 128 * 36;   // [2][128*36]

    const int tid  = threadIdx.x;
    const int lane = tid & 31, wid = tid >> 5;
    const int g = lane >> 2, t = lane & 3;
    const int wm = (wid & 3) * 32, wn = (wid >> 2) * 64;
    const int m0 = bx * 128, n0 = by * 128;

    const int ldrow = tid >> 1, ldc = (tid & 1) * 16;

    float4 pa[4], pb[4];
#pragma unroll
    for (int i = 0; i < 4; i++) {
        pa[i] = *(const float4*)(A  + (size_t)(m0 + ldrow) * EMBD + ldc + 4 * i);
        pb[i] = *(const float4*)(Bw + (size_t)(n0 + ldrow) * EMBD + ldc + 4 * i);
    }
#pragma unroll
    for (int i = 0; i < 4; i++) {
        unsigned* pA = As + ldrow * 36 + ldc + 4 * i;
        pA[0] = f2tf(pa[i].x); pA[1] = f2tf(pa[i].y);
        pA[2] = f2tf(pa[i].z); pA[3] = f2tf(pa[i].w);
        unsigned* pB = Bs + ldrow * 36 + ldc + 4 * i;
        pB[0] = f2tf(pb[i].x); pB[1] = f2tf(pb[i].y);
        pB[2] = f2tf(pb[i].z); pB[3] = f2tf(pb[i].w);
    }
    __syncthreads();

    float acc[2][8][4];
#pragma unroll
    for (int mt = 0; mt < 2; mt++)
#pragma unroll
        for (int nt = 0; nt < 8; nt++)
#pragma unroll
            for (int f = 0; f < 4; f++) acc[mt][nt][f] = 0.f;

    const int NCH = EMBD / 32;
    for (int kc = 0; kc < NCH; kc++) {
        const int cur = kc & 1;
        if (kc + 1 < NCH) {
            int ko = (kc + 1) * 32;
#pragma unroll
            for (int i = 0; i < 4; i++) {
                pa[i] = *(const float4*)(A  + (size_t)(m0 + ldrow) * EMBD + ko + ldc + 4 * i);
                pb[i] = *(const float4*)(Bw + (size_t)(n0 + ldrow) * EMBD + ko + ldc + 4 * i);
            }
        }
        const unsigned* Ac = As + cur * 128 * 36;
        const unsigned* Bc = Bs + cur * 128 * 36;
#pragma unroll
        for (int ks = 0; ks < 4; ks++) {
            const int k = ks * 8;
            unsigned af[2][4], bf[8][2];
#pragma unroll
            for (int mt = 0; mt < 2; mt++) {
                int r = wm + mt * 16 + g;
                af[mt][0] = Ac[r * 36 + k + t];
                af[mt][1] = Ac[(r + 8) * 36 + k + t];
                af[mt][2] = Ac[r * 36 + k + t + 4];
                af[mt][3] = Ac[(r + 8) * 36 + k + t + 4];
            }
#pragma unroll
            for (int nt = 0; nt < 8; nt++) {
                int c = wn + nt * 8 + g;
                bf[nt][0] = Bc[c * 36 + k + t];
                bf[nt][1] = Bc[c * 36 + k + t + 4];
            }
#pragma unroll
            for (int mt = 0; mt < 2; mt++)
#pragma unroll
                for (int nt = 0; nt < 8; nt++)
                    mma8(acc[mt][nt], af[mt], bf[nt]);
        }
        if (kc + 1 < NCH) {
            const int nxt = cur ^ 1;
            unsigned* Ad = As + nxt * 128 * 36;
            unsigned* Bd = Bs + nxt * 128 * 36;
#pragma unroll
            for (int i = 0; i < 4; i++) {
                unsigned* pA = Ad + ldrow * 36 + ldc + 4 * i;
                pA[0] = f2tf(pa[i].x); pA[1] = f2tf(pa[i].y);
                pA[2] = f2tf(pa[i].z); pA[3] = f2tf(pa[i].w);
                unsigned* pB = Bd + ldrow * 36 + ldc + 4 * i;
                pB[0] = f2tf(pb[i].x); pB[1] = f2tf(pb[i].y);
                pB[2] = f2tf(pb[i].z); pB[3] = f2tf(pb[i].w);
            }
        }
        __syncthreads();
    }

    // Epilogue
#pragma unroll
    for (int mt = 0; mt < 2; mt++) {
        int rbase = m0 + wm + mt * 16 + g;
#pragma unroll
        for (int half = 0; half < 2; half++) {
            int r = rbase + half * 8;
#pragma unroll
            for (int nt = 0; nt < 8; nt++) {
                int c = n0 + wn + nt * 8 + 2 * t;
                float v0 = acc[mt][nt][half * 2 + 0] + bias[c];
                float v1 = acc[mt][nt][half * 2 + 1] + bias[c + 1];
                if (SCATTER) {
                    int bb = r >> 11, tt = r & 2047, h = c >> 6, d = c & 63;
                    *(float2*)(out + ((size_t)((bb * NH + h) * TSEQ + tt)) * HDI + d)
                        = make_float2(v0, v1);
                } else {
                    *(float2*)(out + (size_t)r * EMBD + c) = make_float2(v0, v1);
                }
            }
        }
    }
}

__global__ __launch_bounds__(256) void qkv_kernel(
    const float* __restrict__ X,
    const float* __restrict__ Wq, const float* __restrict__ bq,
    const float* __restrict__ Wk, const float* __restrict__ bk,
    const float* __restrict__ Wv, const float* __restrict__ bv)
{
    const float* W; const float* bias; float* out;
    if (blockIdx.z == 0)      { W = Wq; bias = bq; out = g_q; }
    else if (blockIdx.z == 1) { W = Wk; bias = bk; out = g_k; }
    else                      { W = Wv; bias = bv; out = g_v; }
    gemm_body<1>(X, W, bias, out, blockIdx.x, blockIdx.y);
}

__global__ __launch_bounds__(256) void proj_kernel(
    const float* __restrict__ Wo, const float* __restrict__ bo,
    float* __restrict__ out)
{
    gemm_body<0>(g_attn, Wo, bo, out, blockIdx.x, blockIdx.y);
}

// ---------------------------------------------------------------------------
// Flash attention, tf32 mma. q-tile 128 (8 warps x 16 rows), key blocks of 64.
// P stays in registers: C-layout -> A-layout via 4-lane shuffles.
// smem: Qs[128][76] tf32 (Q*0.125), KP[64][76] tf32 (K), Vs[64][72] tf32 (V)
// ---------------------------------------------------------------------------
#define ATTN_SMEM ((128 * 76 + 64 * 76 + 64 * 72) * 4)

__global__ __launch_bounds__(256) void attn_kernel()
{
    extern __shared__ unsigned smu[];
    unsigned* Qs = smu;                       // [128][76]
    unsigned* Ks = smu + 128 * 76;            // [64][76]
    unsigned* Vs = smu + 128 * 76 + 64 * 76;  // [64][72]

    const int tid  = threadIdx.x;
    const int lane = tid & 31, wid = tid >> 5;
    const int g = lane >> 2, t = lane & 3;
    const int bh = blockIdx.y, q0 = blockIdx.x * 128;
    const float* Qg = g_q + (size_t)bh * TSEQ * HDI;
    const float* Kg = g_k + (size_t)bh * TSEQ * HDI;
    const float* Vg = g_v + (size_t)bh * TSEQ * HDI;
    const int qb = wid * 16;  // warp's query-row base (local)

    // Stage Q (scaled by 1/8, tf32)
    {
        int row = tid >> 1, c0 = (tid & 1) * 32;
#pragma unroll
        for (int i = 0; i < 8; i++) {
            float4 v = *(const float4*)(Qg + (size_t)(q0 + row) * HDI + c0 + 4 * i);
            unsigned* p = Qs + row * 76 + c0 + 4 * i;
            p[0] = f2tf(v.x * 0.125f); p[1] = f2tf(v.y * 0.125f);
            p[2] = f2tf(v.z * 0.125f); p[3] = f2tf(v.w * 0.125f);
        }
    }

    float o[8][4];
#pragma unroll
    for (int nt = 0; nt < 8; nt++)
#pragma unroll
        for (int f = 0; f < 4; f++) o[nt][f] = 0.f;
    float m0r = -1e30f, m1r = -1e30f, l0 = 0.f, l1 = 0.f;

    const int krow = tid >> 2, kc0 = (tid & 3) * 16;

    for (int j0 = 0; j0 < TSEQ; j0 += 64) {
        __syncthreads();  // prior block's smem consumers done (and Q staged, iter 0)
        // Stage K, V
#pragma unroll
        for (int i = 0; i < 4; i++) {
            float4 kv = *(const float4*)(Kg + (size_t)(j0 + krow) * HDI + kc0 + 4 * i);
            unsigned* pk = Ks + krow * 76 + kc0 + 4 * i;
            pk[0] = f2tf(kv.x); pk[1] = f2tf(kv.y); pk[2] = f2tf(kv.z); pk[3] = f2tf(kv.w);
            float4 vv = *(const float4*)(Vg + (size_t)(j0 + krow) * HDI + kc0 + 4 * i);
            unsigned* pv = Vs + krow * 72 + kc0 + 4 * i;
            pv[0] = f2tf(vv.x); pv[1] = f2tf(vv.y); pv[2] = f2tf(vv.z); pv[3] = f2tf(vv.w);
        }
        __syncthreads();

        // S = (Q/8) K^T : per warp 16x64 via 8 n-tiles x 8 k-steps
        float s[8][4];
#pragma unroll
        for (int nt = 0; nt < 8; nt++)
#pragma unroll
            for (int f = 0; f < 4; f++) s[nt][f] = 0.f;
#pragma unroll
        for (int ks = 0; ks < 8; ks++) {
            const int k = ks * 8;
            unsigned af[4];
            af[0] = Qs[(qb + g) * 76 + k + t];
            af[1] = Qs[(qb + g + 8) * 76 + k + t];
            af[2] = Qs[(qb + g) * 76 + k + t + 4];
            af[3] = Qs[(qb + g + 8) * 76 + k + t + 4];
#pragma unroll
            for (int nt = 0; nt < 8; nt++) {
                unsigned bf[2];
                bf[0] = Ks[(nt * 8 + g) * 76 + k + t];
                bf[1] = Ks[(nt * 8 + g) * 76 + k + t + 4];
                mma8(s[nt], af, bf);
            }
        }

        // Online softmax. Thread owns rows (qb+g): frags {0,1}; (qb+g+8): {2,3}.
        float mx0 = -1e30f, mx1 = -1e30f;
#pragma unroll
        for (int nt = 0; nt < 8; nt++) {
            mx0 = fmaxf(mx0, fmaxf(s[nt][0], s[nt][1]));
            mx1 = fmaxf(mx1, fmaxf(s[nt][2], s[nt][3]));
        }
#pragma unroll
        for (int off = 1; off <= 2; off <<= 1) {
            mx0 = fmaxf(mx0, __shfl_xor_sync(0xffffffffu, mx0, off));
            mx1 = fmaxf(mx1, __shfl_xor_sync(0xffffffffu, mx1, off));
        }
        float M0 = fmaxf(m0r, mx0), M1 = fmaxf(m1r, mx1);
        float al0 = __expf(m0r - M0), al1 = __expf(m1r - M1);
        float rs0 = 0.f, rs1 = 0.f;
#pragma unroll
        for (int nt = 0; nt < 8; nt++) {
            s[nt][0] = __expf(s[nt][0] - M0); rs0 += s[nt][0];
            s[nt][1] = __expf(s[nt][1] - M0); rs0 += s[nt][1];
            s[nt][2] = __expf(s[nt][2] - M1); rs1 += s[nt][2];
            s[nt][3] = __expf(s[nt][3] - M1); rs1 += s[nt][3];
        }
#pragma unroll
        for (int off = 1; off <= 2; off <<= 1) {
            rs0 += __shfl_xor_sync(0xffffffffu, rs0, off);
            rs1 += __shfl_xor_sync(0xffffffffu, rs1, off);
        }
        l0 = l0 * al0 + rs0; l1 = l1 * al1 + rs1;
        m0r = M0; m1r = M1;
#pragma unroll
        for (int nt = 0; nt < 8; nt++) {
            o[nt][0] *= al0; o[nt][1] *= al0;
            o[nt][2] *= al1; o[nt][3] *= al1;
        }

        // O += P V. P fragment built from s[] via 4-lane shuffles:
        // C-layout cols {2t,2t+1} -> A-layout cols {t, t+4}.
        const int lo = (lane & ~3) | (t >> 1);
        const int hi = lo + 2;
        const bool odd = (t & 1);
#pragma unroll
        for (int ks = 0; ks < 8; ks++) {
            float p0 = __shfl_sync(0xffffffffu, s[ks][0], lo);
            float p1 = __shfl_sync(0xffffffffu, s[ks][1], lo);
            float q0f = __shfl_sync(0xffffffffu, s[ks][0], hi);
            float q1f = __shfl_sync(0xffffffffu, s[ks][1], hi);
            float r0 = __shfl_sync(0xffffffffu, s[ks][2], lo);
            float r1 = __shfl_sync(0xffffffffu, s[ks][3], lo);
            float u0 = __shfl_sync(0xffffffffu, s[ks][2], hi);
            float u1 = __shfl_sync(0xffffffffu, s[ks][3], hi);
            unsigned af[4];
            af[0] = f2tf(odd ? p1 : p0);
            af[1] = f2tf(odd ? r1 : r0);
            af[2] = f2tf(odd ? q1f : q0f);
            af[3] = f2tf(odd ? u1 : u0);
#pragma unroll
            for (int nt = 0; nt < 8; nt++) {
                unsigned bf[2];
                bf[0] = Vs[(ks * 8 + t) * 72 + nt * 8 + g];
                bf[1] = Vs[(ks * 8 + t + 4) * 72 + nt * 8 + g];
                mma8(o[nt], af, bf);
            }
        }
    }

    // Write back: [B,T,EMB] row-major for out-proj
    const int b = bh >> 4, h = bh & 15;
    float inv0 = 1.f / l0, inv1 = 1.f / l1;
    int r0 = q0 + qb + g, r1 = r0 + 8;
#pragma unroll
    for (int nt = 0; nt < 8; nt++) {
        int c = h * HDI + nt * 8 + 2 * t;
        *(float2*)(g_attn + (size_t)(b * TSEQ + r0) * EMBD + c)
            = make_float2(o[nt][0] * inv0, o[nt][1] * inv0);
        *(float2*)(g_attn + (size_t)(b * TSEQ + r1) * EMBD + c)
            = make_float2(o[nt][2] * inv1, o[nt][3] * inv1);
    }
}

// ---------------------------------------------------------------------------
extern "C" void kernel_launch(void* const* d_in, const int* in_sizes, int n_in,
                              void* d_out, int out_size)
{
    const float* x  = (const float*)d_in[0];
    const float* Wq = (const float*)d_in[1];
    const float* bq = (const float*)d_in[2];
    const float* Wk = (const float*)d_in[3];
    const float* bk = (const float*)d_in[4];
    const float* Wv = (const float*)d_in[5];
    const float* bv = (const float*)d_in[6];
    const float* Wo = (const float*)d_in[7];
    const float* bo = (const float*)d_in[8];
    float* out = (float*)d_out;

    static int inited = 0;
    if (!inited) {
        cudaFuncSetAttribute(qkv_kernel,  cudaFuncAttributeMaxDynamicSharedMemorySize, GEMM_SMEM);
        cudaFuncSetAttribute(proj_kernel, cudaFuncAttributeMaxDynamicSharedMemorySize, GEMM_SMEM);
        cudaFuncSetAttribute(attn_kernel, cudaFuncAttributeMaxDynamicSharedMemorySize, ATTN_SMEM);
        inited = 1;
    }

    dim3 gq(M_TOT / 128, EMBD / 128, 3);
    qkv_kernel<<<gq, 256, GEMM_SMEM>>>(x, Wq, bq, Wk, bk, Wv, bv);

    dim3 ga(TSEQ / 128, NB * NH);
    attn_kernel<<<ga, 256, ATTN_SMEM>>>();

    dim3 go(M_TOT / 128, EMBD / 128);
    proj_kernel<<<go, 256, GEMM_SMEM>>>(Wo, bo, out);
}